// round 12
// baseline (speedup 1.0000x reference)
#include <cuda_runtime.h>
#include <cuda_fp16.h>
#include <cstdint>
#include <cstddef>

#define T_DIM   8
#define N_NODES 50000
#define E_EDGES 800000
#define C_DIM   64
#define M_ROWS  (T_DIM * N_NODES)   // 400000 rows of [x | tx1]
#define TILES   (M_ROWS / 128)      // 3125 (= 50000/16 node-groups)
#define GRID_GEMM 148
#define BCAP    64                   // bucket capacity per node (P(deg>64) ~ 0)

// ---------------- scratch (static device globals; no allocation) ----------------
// g_deg / g_cnt are zeroed by the fused kernel's gather (each node once) for the
// NEXT invocation; module load provides the initial zeros.
__device__ float   g_deg[N_NODES];
__device__ int     g_cnt[N_NODES];
__device__ uint2   g_cv[(size_t)N_NODES * BCAP];        // packed (col,val) buckets
// node-major fp16 x: [node][t][32 half2] — 1KB per node
__device__ __half2 g_xh[(size_t)M_ROWS * (C_DIM/2)];    // 51.2 MB

// ---------------- prep0: x -> fp16 node-major transpose + deg atomics (fused) ----------------
__global__ void k_prep0(const float* __restrict__ x,
                        const int* __restrict__ ei, const float* __restrict__ ew) {
    size_t i = (size_t)blockIdx.x * blockDim.x + threadIdx.x;
    if (i < (size_t)E_EDGES) {
        int e = (int)i;
        atomicAdd(&g_deg[ei[e]], ew[e]);
    }
    if (i < (size_t)M_ROWS * (C_DIM / 2)) {
        int c    = (int)(i & 31);
        int rest = (int)(i >> 5);          // t*N + n
        int t = rest / N_NODES;
        int n = rest - t * N_NODES;
        float2 v = ((const float2*)x)[i];
        g_xh[((size_t)n * T_DIM + t) * 32 + c] = __floats2half2_rn(v.x, v.y);
    }
}

// ---------------- bucket fill ----------------
__device__ __forceinline__ float dinv_of(float dg) {
    return (dg > 0.f) ? rsqrtf(fmaxf(dg, 1e-12f)) : 0.f;
}

__global__ void k_fill(const int* __restrict__ ei, const float* __restrict__ ew) {
    int e = blockIdx.x * blockDim.x + threadIdx.x;
    if (e < E_EDGES) {
        int s = ei[e];
        int d = ei[E_EDGES + e];
        float nw = -ew[e] * dinv_of(g_deg[s]) * dinv_of(g_deg[d]);
        int p = atomicAdd(&g_cnt[d], 1);
        if (p < BCAP) {
            uint2 cv;
            cv.x = (uint32_t)s;
            cv.y = __float_as_uint(nw);
            g_cv[((size_t)d << 6) + p] = cv;
        }
    }
}

// ============================================================================
// FUSED gather + HMMA GEMM — 512 threads, persistent 148 CTAs.
// Tile = 128 rows = 16 nodes x 8 timesteps. Warp w gathers node tile*16+w
// directly into the smem A-buffer (tx1 half, cols 64..127); x half arrives
// via cp.async. Per iteration: gather(t+1) then mma(t) — gather latency and
// warp imbalance overlap with tensor work.
// ============================================================================

#define ASTRIDE 272u
#define ATILE   (128u * ASTRIDE)
#define OFF_W   (2u * ATILE)
#define DSMEM_BYTES (3u * ATILE)    // 2 A bufs + W = 104448
#define GTHREADS 512

#define CP_ASYNC16(dst, src) \
    asm volatile("cp.async.cg.shared.global [%0], [%1], 16;" :: "r"(dst), "l"(src))
#define CP_COMMIT() asm volatile("cp.async.commit_group;" ::: "memory")
#define CP_WAIT(n)  asm volatile("cp.async.wait_group %0;" :: "n"(n) : "memory")

__device__ __forceinline__ void mma_fp16(float* c, const uint32_t* a,
                                         uint32_t b0, uint32_t b1) {
    asm volatile(
        "mma.sync.aligned.m16n8k16.row.col.f32.f16.f16.f32 "
        "{%0,%1,%2,%3}, {%4,%5,%6,%7}, {%8,%9}, {%0,%1,%2,%3};"
        : "+f"(c[0]), "+f"(c[1]), "+f"(c[2]), "+f"(c[3])
        : "r"(a[0]), "r"(a[1]), "r"(a[2]), "r"(a[3]), "r"(b0), "r"(b1));
}

__device__ __forceinline__ void ldsm_x4(uint32_t* d, uint32_t addr) {
    asm volatile("ldmatrix.sync.aligned.m8n8.x4.shared.b16 {%0,%1,%2,%3}, [%4];"
                 : "=r"(d[0]), "=r"(d[1]), "=r"(d[2]), "=r"(d[3]) : "r"(addr));
}

// cp.async the x half (cols 0..63) of one tile into smem buffer
__device__ __forceinline__ void prefetchX(int tile, uint32_t dstBase, int tid) {
    int rowBase = tile * 128;
    #pragma unroll
    for (int it = 0; it < 2; it++) {
        int chunk = tid + it * GTHREADS;   // 0..1023 chunks of 16B
        int r  = chunk >> 3;
        int c16 = chunk & 7;
        const void* src = (const void*)(g_xh + (size_t)(rowBase + r) * 32 + c16 * 4);
        uint32_t dst = dstBase + (uint32_t)r * ASTRIDE + (uint32_t)c16 * 16u;
        CP_ASYNC16(dst, src);
    }
    CP_COMMIT();
}

// gather one node's tx1 (fp16) straight into the smem A-buffer.
// lane owns 32B: t = lane>>2, channel bytes (lane&3)*32 of the 128B t-row.
__device__ __forceinline__ void gatherNode(int tile, char* buf, int wid, int lane) {
    int node = tile * 16 + wid;
    int cnt = 0;
    if (lane == 0) {
        cnt = g_cnt[node];
        g_cnt[node] = 0;        // recycle for next invocation
        g_deg[node] = 0.f;
    }
    cnt = __shfl_sync(0xffffffffu, cnt, 0);
    if (cnt > BCAP) cnt = BCAP;
    const uint2* __restrict__ bucket = g_cv + ((size_t)node << 6);

    float2 acc[8];
    #pragma unroll
    for (int q = 0; q < 8; q++) acc[q] = make_float2(0.f, 0.f);

    const char* xbase = (const char*)g_xh + (size_t)lane * 32;

    int e = 0;
    for (; e + 1 < cnt; e += 2) {
        uint2 cv0 = __ldg(&bucket[e]);
        uint2 cv1 = __ldg(&bucket[e + 1]);
        float v0 = __uint_as_float(cv0.y);
        float v1 = __uint_as_float(cv1.y);
        const uint4* p0 = (const uint4*)(xbase + (size_t)cv0.x * 1024);
        const uint4* p1 = (const uint4*)(xbase + (size_t)cv1.x * 1024);
        uint4 a0 = __ldg(p0), b0 = __ldg(p0 + 1);
        uint4 a1 = __ldg(p1), b1 = __ldg(p1 + 1);
        const uint32_t* w0 = (const uint32_t*)&a0;
        const uint32_t* u0 = (const uint32_t*)&b0;
        const uint32_t* w1 = (const uint32_t*)&a1;
        const uint32_t* u1 = (const uint32_t*)&b1;
        #pragma unroll
        for (int q = 0; q < 4; q++) {
            float2 f;
            f = __half22float2(*(const __half2*)&w0[q]);
            acc[q].x = fmaf(v0, f.x, acc[q].x); acc[q].y = fmaf(v0, f.y, acc[q].y);
            f = __half22float2(*(const __half2*)&u0[q]);
            acc[4+q].x = fmaf(v0, f.x, acc[4+q].x); acc[4+q].y = fmaf(v0, f.y, acc[4+q].y);
            f = __half22float2(*(const __half2*)&w1[q]);
            acc[q].x = fmaf(v1, f.x, acc[q].x); acc[q].y = fmaf(v1, f.y, acc[q].y);
            f = __half22float2(*(const __half2*)&u1[q]);
            acc[4+q].x = fmaf(v1, f.x, acc[4+q].x); acc[4+q].y = fmaf(v1, f.y, acc[4+q].y);
        }
    }
    if (e < cnt) {
        uint2 cv0 = __ldg(&bucket[e]);
        float v0 = __uint_as_float(cv0.y);
        const uint4* p0 = (const uint4*)(xbase + (size_t)cv0.x * 1024);
        uint4 a0 = __ldg(p0), b0 = __ldg(p0 + 1);
        const uint32_t* w0 = (const uint32_t*)&a0;
        const uint32_t* u0 = (const uint32_t*)&b0;
        #pragma unroll
        for (int q = 0; q < 4; q++) {
            float2 f;
            f = __half22float2(*(const __half2*)&w0[q]);
            acc[q].x = fmaf(v0, f.x, acc[q].x); acc[q].y = fmaf(v0, f.y, acc[q].y);
            f = __half22float2(*(const __half2*)&u0[q]);
            acc[4+q].x = fmaf(v0, f.x, acc[4+q].x); acc[4+q].y = fmaf(v0, f.y, acc[4+q].y);
        }
    }

    uint4 o0, o1;
    uint32_t* w = (uint32_t*)&o0;
    uint32_t* u = (uint32_t*)&o1;
    #pragma unroll
    for (int q = 0; q < 4; q++) {
        __half2 h0 = __floats2half2_rn(acc[q].x, acc[q].y);
        __half2 h1 = __floats2half2_rn(acc[4+q].x, acc[4+q].y);
        w[q] = *(uint32_t*)&h0;
        u[q] = *(uint32_t*)&h1;
    }
    // A-tile row = wid*8 + t, tx1 half starts at byte 128 of the row
    char* dst = buf + (uint32_t)(wid * 8 + (lane >> 2)) * ASTRIDE
                    + 128u + (uint32_t)(lane & 3) * 32u;
    *(uint4*)dst        = o0;
    *(uint4*)(dst + 16) = o1;
}

__global__ void __launch_bounds__(GTHREADS, 1) k_fused(
    const float* __restrict__ Wxz0, const float* __restrict__ Wxz1,
    const float* __restrict__ Wxh0, const float* __restrict__ Wxh1,
    const float* __restrict__ bxz,  const float* __restrict__ bhz,
    const float* __restrict__ bxh,  const float* __restrict__ bhh,
    const float* __restrict__ wlin, const float* __restrict__ blin,
    float* __restrict__ out)
{
    extern __shared__ char dsm[];
    __shared__ float sBZ[64], sBH[64], sWl[64];
    __shared__ float sRed[128][4];

    char* WTh = dsm + OFF_W;
    uint32_t smemBase = (uint32_t)__cvta_generic_to_shared(dsm);
    uint32_t smemW32  = smemBase + OFF_W;

    int tid  = threadIdx.x;
    int wid  = tid >> 5;
    int lane = tid & 31;
    int bid  = blockIdx.x;
    int n = (TILES - bid + GRID_GEMM - 1) / GRID_GEMM;

    int wm = wid >> 2;           // 0..3 : rows wm*32 ..
    int wn = wid & 3;            // 0..3 : Z cols wn*16.., H cols 64+wn*16..

    // combined weights, transposed WT[n][k] = Wcomb[k][n], fp16
    for (int idx = tid; idx < 16384; idx += GTHREADS) {
        int nn = idx >> 7;
        int k  = idx & 127;
        float v;
        if (k < 64) v = (nn < 64) ? Wxz0[k * 64 + nn]        : Wxh0[k * 64 + (nn - 64)];
        else        v = (nn < 64) ? Wxz1[(k - 64) * 64 + nn] : Wxh1[(k - 64) * 64 + (nn - 64)];
        *(__half*)(WTh + (uint32_t)nn * ASTRIDE + (uint32_t)k * 2u) = __float2half_rn(v);
    }
    if (tid < 64) {
        sBZ[tid] = bxz[tid] + bhz[tid];
        sBH[tid] = bxh[tid] + bhh[tid];
        sWl[tid] = wlin[tid];
    }
    float blin0 = blin[0];

    // ldmatrix per-lane addresses
    uint32_t aOff[2];   // relative to A-buffer base
    uint32_t bAddr[2];  // absolute (W tile fixed)
    {
        int m = lane >> 3, r = lane & 7;
        #pragma unroll
        for (int mt = 0; mt < 2; mt++) {
            int rowA = wm * 32 + mt * 16 + ((m & 1) << 3) + r;
            aOff[mt] = (uint32_t)rowA * ASTRIDE + (uint32_t)((m >> 1) << 4);
        }
        int q = lane >> 3;
        #pragma unroll
        for (int g = 0; g < 2; g++) {
            int nt  = g * 2 + (q >> 1);
            int col = wn * 16 + ((nt & 1) << 3) + ((nt >> 1) << 6);
            bAddr[g] = smemW32 + (uint32_t)(col + r) * ASTRIDE + (uint32_t)((q & 1) << 4);
        }
    }

    // prologue: tile 0 into buf0 (x via cp.async group0, tx1 via gather)
    prefetchX(bid, smemBase, tid);
    gatherNode(bid, dsm, wid, lane);

    for (int t = 0; t < n; t++) {
        __syncthreads();   // buf[t] fully gathered; buf[t+1] free of readers

        if (t + 1 < n) {
            int tile1 = bid + (t + 1) * GRID_GEMM;
            uint32_t nbuf = (uint32_t)((t + 1) & 1) * ATILE;
            prefetchX(tile1, smemBase + nbuf, tid);
            gatherNode(tile1, dsm + nbuf, wid, lane);
            CP_WAIT(1);    // group t complete (buf[t] x ready); t+1 pending
        } else {
            CP_WAIT(0);
        }

        uint32_t aBuf = smemBase + (uint32_t)(t & 1) * ATILE;

        float acc[2][4][4];
        #pragma unroll
        for (int mt = 0; mt < 2; mt++)
            #pragma unroll
            for (int nt = 0; nt < 4; nt++)
                #pragma unroll
                for (int q = 0; q < 4; q++) acc[mt][nt][q] = 0.f;

        #pragma unroll
        for (int ks = 0; ks < 8; ks++) {
            uint32_t kkb = (uint32_t)ks * 32u;
            uint32_t a[2][4], B[2][4];
            ldsm_x4(a[0], aBuf + aOff[0] + kkb);
            ldsm_x4(a[1], aBuf + aOff[1] + kkb);
            ldsm_x4(B[0], bAddr[0] + kkb);
            ldsm_x4(B[1], bAddr[1] + kkb);
            #pragma unroll
            for (int nt = 0; nt < 4; nt++) {
                uint32_t b0 = B[nt >> 1][(nt & 1) * 2];
                uint32_t b1 = B[nt >> 1][(nt & 1) * 2 + 1];
                mma_fp16(acc[0][nt], a[0], b0, b1);
                mma_fp16(acc[1][nt], a[1], b0, b1);
            }
        }

        // register epilogue: act + projection
        int rA = lane >> 2;
        int cA = (lane & 3) * 2;
        float s0[2], s1[2];
        #pragma unroll
        for (int mt = 0; mt < 2; mt++) { s0[mt] = 0.f; s1[mt] = 0.f; }
        #pragma unroll
        for (int mt = 0; mt < 2; mt++) {
            #pragma unroll
            for (int ntc = 0; ntc < 2; ntc++) {
                const float* aZ = acc[mt][ntc];
                const float* aH = acc[mt][ntc + 2];
                int cbase = wn * 16 + ntc * 8 + cA;
                #pragma unroll
                for (int u = 0; u < 2; u++) {
                    int c = cbase + u;
                    float bz = sBZ[c], bh = sBH[c], w = sWl[c];
                    {
                        float A = aZ[u] + bz, Bv = aH[u] + bh;
                        float z  = __fdividef(1.f, 1.f + __expf(-A));
                        float e2 = __expf(2.f * Bv);
                        float th = 1.f - __fdividef(2.f, e2 + 1.f);
                        s0[mt] = fmaf(fmaxf((1.f - z) * th, 0.f), w, s0[mt]);
                    }
                    {
                        float A = aZ[2 + u] + bz, Bv = aH[2 + u] + bh;
                        float z  = __fdividef(1.f, 1.f + __expf(-A));
                        float e2 = __expf(2.f * Bv);
                        float th = 1.f - __fdividef(2.f, e2 + 1.f);
                        s1[mt] = fmaf(fmaxf((1.f - z) * th, 0.f), w, s1[mt]);
                    }
                }
            }
        }
        #pragma unroll
        for (int mt = 0; mt < 2; mt++) {
            s0[mt] += __shfl_xor_sync(0xffffffffu, s0[mt], 1);
            s0[mt] += __shfl_xor_sync(0xffffffffu, s0[mt], 2);
            s1[mt] += __shfl_xor_sync(0xffffffffu, s1[mt], 1);
            s1[mt] += __shfl_xor_sync(0xffffffffu, s1[mt], 2);
        }
        if ((lane & 3) == 0) {
            #pragma unroll
            for (int mt = 0; mt < 2; mt++) {
                int r = wm * 32 + mt * 16 + rA;
                sRed[r][wn]     = s0[mt];
                sRed[r + 8][wn] = s1[mt];
            }
        }
        __syncthreads();
        if (tid < 128) {
            float v = sRed[tid][0] + sRed[tid][1] + sRed[tid][2] + sRed[tid][3];
            int rg   = (bid + t * GRID_GEMM) * 128 + tid;   // row' = node*8 + tt
            int node = rg >> 3;
            int tt   = rg & 7;
            out[tt * N_NODES + node] = v + blin0;
        }
    }
}

// ---------------- launch ----------------
extern "C" void kernel_launch(void* const* d_in, const int* in_sizes, int n_in,
                              void* d_out, int out_size)
{
    const float* x    = (const float*)d_in[0];
    const int*   ei   = (const int*)  d_in[1];
    const float* ew   = (const float*)d_in[2];
    const float* Wxz0 = (const float*)d_in[3];
    const float* Wxz1 = (const float*)d_in[4];
    const float* bxz  = (const float*)d_in[5];
    const float* bhz  = (const float*)d_in[8];
    const float* Wxh0 = (const float*)d_in[15];
    const float* Wxh1 = (const float*)d_in[16];
    const float* bxh  = (const float*)d_in[17];
    const float* bhh  = (const float*)d_in[20];
    const float* Wlin = (const float*)d_in[21];
    const float* blin = (const float*)d_in[22];
    float* out = (float*)d_out;

    cudaFuncSetAttribute(k_fused, cudaFuncAttributeMaxDynamicSharedMemorySize, DSMEM_BYTES);

    const int NB_E = (E_EDGES + 255) / 256;
    const int NB_X = (int)(((size_t)M_ROWS * (C_DIM / 2) + 255) / 256);

    k_prep0 <<<NB_X, 256>>>(x, ei, ew);    // 1: x->fp16 transpose + deg atomics
    k_fill  <<<NB_E, 256>>>(ei, ew);       // 2: bucket fill
    k_fused <<<GRID_GEMM, GTHREADS, DSMEM_BYTES>>>(Wxz0, Wxz1, Wxh0, Wxh1,
                                                   bxz, bhz, bxh, bhh, Wlin, blin, out);
}

// round 13
// speedup vs baseline: 1.1866x; 1.1866x over previous
#include <cuda_runtime.h>
#include <cuda_fp16.h>
#include <cstdint>
#include <cstddef>

#define T_DIM   8
#define N_NODES 50000
#define E_EDGES 800000
#define C_DIM   64
#define M_ROWS  (T_DIM * N_NODES)   // 400000 rows of [x | tx1]
#define TILES   (M_ROWS / 128)      // 3125
#define GRID_GEMM 148
#define BCAP    64                   // bucket capacity per node (P(deg>64) ~ 0)

// ---------------- scratch (static device globals; no allocation) ----------------
// g_deg / g_cnt are zeroed by k_gemm at the END of each invocation (and are
// zero at module load), so the prep path needs no separate zeroing kernel.
__device__ float   g_deg[N_NODES];
__device__ int     g_cnt[N_NODES];
__device__ uint2   g_cv[(size_t)N_NODES * BCAP];        // packed (col,val) buckets
// node-major fp16: [node][t][32 half2] — 1KB per node
__device__ __half2 g_xh  [(size_t)M_ROWS * (C_DIM/2)];  // 51.2 MB
__device__ __half2 g_tx1h[(size_t)M_ROWS * (C_DIM/2)];  // 51.2 MB

// ---------------- prep0: x -> fp16 node-major transpose (16B chunks, no IDIV)
//                  + deg atomics (fused) ----------------
#define XCHUNKS (M_ROWS * 8)   // 3.2M 16-byte output chunks

__global__ void k_prep0(const float4* __restrict__ x4,
                        const int* __restrict__ ei, const float* __restrict__ ew) {
    int j = blockIdx.x * blockDim.x + threadIdx.x;
    if (j < E_EDGES) {
        atomicAdd(&g_deg[ei[j]], ew[j]);     // g_deg pre-zeroed by prior k_gemm
    }
    if (j < XCHUNKS) {
        int c4 = j & 7;          // which 16B chunk within the 128B t-row
        int r  = j >> 3;         // node-major row = n*8 + t
        int n  = r >> 3;
        int t  = r & 7;
        size_t s = ((size_t)t * N_NODES + n) * 16 + (size_t)c4 * 2;
        float4 v0 = __ldg(&x4[s]);
        float4 v1 = __ldg(&x4[s + 1]);
        uint4 o;
        __half2 h;
        h = __floats2half2_rn(v0.x, v0.y); o.x = *(uint32_t*)&h;
        h = __floats2half2_rn(v0.z, v0.w); o.y = *(uint32_t*)&h;
        h = __floats2half2_rn(v1.x, v1.y); o.z = *(uint32_t*)&h;
        h = __floats2half2_rn(v1.z, v1.w); o.w = *(uint32_t*)&h;
        ((uint4*)g_xh)[j] = o;
    }
}

// ---------------- bucket fill: slot via atomic cnt, packed (col,val) STG.64 ----------------
__device__ __forceinline__ float dinv_of(float dg) {
    return (dg > 0.f) ? rsqrtf(fmaxf(dg, 1e-12f)) : 0.f;
}

__global__ void k_fill(const int* __restrict__ ei, const float* __restrict__ ew) {
    int e = blockIdx.x * blockDim.x + threadIdx.x;
    if (e < E_EDGES) {
        int s = ei[e];
        int d = ei[E_EDGES + e];
        float nw = -ew[e] * dinv_of(g_deg[s]) * dinv_of(g_deg[d]);
        int p = atomicAdd(&g_cnt[d], 1);   // g_cnt pre-zeroed by prior k_gemm
        if (p < BCAP) {
            uint2 cv;
            cv.x = (uint32_t)s;
            cv.y = __float_as_uint(nw);
            g_cv[((size_t)d << 6) + p] = cv;
        }
    }
}

// ---------------- gather (R8 winner): one warp per dst node, lane owns 32B slice ----------------
__global__ void k_gather() {
    int warp = (blockIdx.x * blockDim.x + threadIdx.x) >> 5;
    int lane = threadIdx.x & 31;
    if (warp >= N_NODES) return;
    int cnt = g_cnt[warp];
    if (cnt > BCAP) cnt = BCAP;
    const uint2* __restrict__ bucket = g_cv + ((size_t)warp << 6);

    float2 acc[8];
    #pragma unroll
    for (int q = 0; q < 8; q++) acc[q] = make_float2(0.f, 0.f);

    const char* xbase = (const char*)g_xh + (size_t)lane * 32;

    int e = 0;
    for (; e + 1 < cnt; e += 2) {
        uint2 cv0 = __ldg(&bucket[e]);
        uint2 cv1 = __ldg(&bucket[e + 1]);
        float v0 = __uint_as_float(cv0.y);
        float v1 = __uint_as_float(cv1.y);
        const uint4* p0 = (const uint4*)(xbase + (size_t)cv0.x * 1024);
        const uint4* p1 = (const uint4*)(xbase + (size_t)cv1.x * 1024);
        uint4 a0 = __ldg(p0), b0 = __ldg(p0 + 1);
        uint4 a1 = __ldg(p1), b1 = __ldg(p1 + 1);
        const uint32_t* w0 = (const uint32_t*)&a0;
        const uint32_t* u0 = (const uint32_t*)&b0;
        const uint32_t* w1 = (const uint32_t*)&a1;
        const uint32_t* u1 = (const uint32_t*)&b1;
        #pragma unroll
        for (int q = 0; q < 4; q++) {
            float2 f;
            f = __half22float2(*(const __half2*)&w0[q]);
            acc[q].x = fmaf(v0, f.x, acc[q].x); acc[q].y = fmaf(v0, f.y, acc[q].y);
            f = __half22float2(*(const __half2*)&u0[q]);
            acc[4+q].x = fmaf(v0, f.x, acc[4+q].x); acc[4+q].y = fmaf(v0, f.y, acc[4+q].y);
            f = __half22float2(*(const __half2*)&w1[q]);
            acc[q].x = fmaf(v1, f.x, acc[q].x); acc[q].y = fmaf(v1, f.y, acc[q].y);
            f = __half22float2(*(const __half2*)&u1[q]);
            acc[4+q].x = fmaf(v1, f.x, acc[4+q].x); acc[4+q].y = fmaf(v1, f.y, acc[4+q].y);
        }
    }
    if (e < cnt) {
        uint2 cv0 = __ldg(&bucket[e]);
        float v0 = __uint_as_float(cv0.y);
        const uint4* p0 = (const uint4*)(xbase + (size_t)cv0.x * 1024);
        uint4 a0 = __ldg(p0), b0 = __ldg(p0 + 1);
        const uint32_t* w0 = (const uint32_t*)&a0;
        const uint32_t* u0 = (const uint32_t*)&b0;
        #pragma unroll
        for (int q = 0; q < 4; q++) {
            float2 f;
            f = __half22float2(*(const __half2*)&w0[q]);
            acc[q].x = fmaf(v0, f.x, acc[q].x); acc[q].y = fmaf(v0, f.y, acc[q].y);
            f = __half22float2(*(const __half2*)&u0[q]);
            acc[4+q].x = fmaf(v0, f.x, acc[4+q].x); acc[4+q].y = fmaf(v0, f.y, acc[4+q].y);
        }
    }

    uint4 o0, o1;
    uint32_t* w = (uint32_t*)&o0;
    uint32_t* u = (uint32_t*)&o1;
    #pragma unroll
    for (int q = 0; q < 4; q++) {
        __half2 h0 = __floats2half2_rn(acc[q].x, acc[q].y);
        __half2 h1 = __floats2half2_rn(acc[4+q].x, acc[4+q].y);
        w[q] = *(uint32_t*)&h0;
        u[q] = *(uint32_t*)&h1;
    }
    uint4* op = (uint4*)((char*)g_tx1h + (size_t)warp * 1024 + (size_t)lane * 32);
    op[0] = o0;
    op[1] = o1;
}

// ============================================================================
// HMMA fp16 GEMM — 512 threads, 128x128 tile, warp = 32x32, ldmatrix frags,
// 2-stage cp.async double buffer. Zeroes g_cnt/g_deg for next invocation.
// ============================================================================

#define ASTRIDE 272u
#define ATILE   (128u * ASTRIDE)
#define NBUF    2
#define OFF_W   (NBUF * ATILE)
#define DSMEM_BYTES (NBUF * ATILE + ATILE)   // 104448
#define GTHREADS 512

#define CP_ASYNC16(dst, src) \
    asm volatile("cp.async.cg.shared.global [%0], [%1], 16;" :: "r"(dst), "l"(src))
#define CP_COMMIT() asm volatile("cp.async.commit_group;" ::: "memory")
#define CP_WAIT(n)  asm volatile("cp.async.wait_group %0;" :: "n"(n) : "memory")

__device__ __forceinline__ void mma_fp16(float* c, const uint32_t* a,
                                         uint32_t b0, uint32_t b1) {
    asm volatile(
        "mma.sync.aligned.m16n8k16.row.col.f32.f16.f16.f32 "
        "{%0,%1,%2,%3}, {%4,%5,%6,%7}, {%8,%9}, {%0,%1,%2,%3};"
        : "+f"(c[0]), "+f"(c[1]), "+f"(c[2]), "+f"(c[3])
        : "r"(a[0]), "r"(a[1]), "r"(a[2]), "r"(a[3]), "r"(b0), "r"(b1));
}

__device__ __forceinline__ void ldsm_x4(uint32_t* d, uint32_t addr) {
    asm volatile("ldmatrix.sync.aligned.m8n8.x4.shared.b16 {%0,%1,%2,%3}, [%4];"
                 : "=r"(d[0]), "=r"(d[1]), "=r"(d[2]), "=r"(d[3]) : "r"(addr));
}

__device__ __forceinline__ void prefetchA(int tile, uint32_t dstBase, int tid) {
    int rowBase = tile * 128;
    #pragma unroll
    for (int it = 0; it < 4; it++) {
        int chunk = tid + it * GTHREADS;   // 0..2047 chunks of 16B
        int r   = chunk >> 4;
        int c16 = chunk & 15;
        size_t row = (size_t)(rowBase + r);
        const void* src = (c16 < 8)
            ? (const void*)(g_xh   + row * 32 + c16 * 4)
            : (const void*)(g_tx1h + row * 32 + (c16 - 8) * 4);
        uint32_t dst = dstBase + (uint32_t)r * ASTRIDE + (uint32_t)c16 * 16u;
        CP_ASYNC16(dst, src);
    }
    CP_COMMIT();
}

__global__ void __launch_bounds__(GTHREADS, 1) k_gemm(
    const float* __restrict__ Wxz0, const float* __restrict__ Wxz1,
    const float* __restrict__ Wxh0, const float* __restrict__ Wxh1,
    const float* __restrict__ bxz,  const float* __restrict__ bhz,
    const float* __restrict__ bxh,  const float* __restrict__ bhh,
    const float* __restrict__ wlin, const float* __restrict__ blin,
    float* __restrict__ out)
{
    extern __shared__ char dsm[];
    __shared__ float sBZ[64], sBH[64], sWl[64];
    __shared__ float sRed[128][4];

    char* WTh = dsm + OFF_W;
    uint32_t smemBase = (uint32_t)__cvta_generic_to_shared(dsm);
    uint32_t smemW32  = smemBase + OFF_W;

    int tid  = threadIdx.x;
    int wid  = tid >> 5;
    int lane = tid & 31;
    int bid  = blockIdx.x;
    int n = (TILES - bid + GRID_GEMM - 1) / GRID_GEMM;

    // zero cnt/deg for the NEXT kernel_launch invocation
    for (int i = bid * GTHREADS + tid; i < N_NODES; i += GRID_GEMM * GTHREADS) {
        g_cnt[i] = 0;
        g_deg[i] = 0.f;
    }

    int wm = wid >> 2;           // 0..3 : rows wm*32 ..
    int wn = wid & 3;            // 0..3 : Z cols wn*16.., H cols 64+wn*16..

    for (int idx = tid; idx < 16384; idx += GTHREADS) {
        int nn = idx >> 7;
        int k  = idx & 127;
        float v;
        if (k < 64) v = (nn < 64) ? Wxz0[k * 64 + nn]        : Wxh0[k * 64 + (nn - 64)];
        else        v = (nn < 64) ? Wxz1[(k - 64) * 64 + nn] : Wxh1[(k - 64) * 64 + (nn - 64)];
        *(__half*)(WTh + (uint32_t)nn * ASTRIDE + (uint32_t)k * 2u) = __float2half_rn(v);
    }
    if (tid < 64) {
        sBZ[tid] = bxz[tid] + bhz[tid];
        sBH[tid] = bxh[tid] + bhh[tid];
        sWl[tid] = wlin[tid];
    }
    float blin0 = blin[0];

    // ldmatrix per-lane addresses
    uint32_t aOff[2];   // relative to A-buffer base
    uint32_t bAddr[2];  // absolute (W tile fixed)
    {
        int m = lane >> 3, r = lane & 7;
        #pragma unroll
        for (int mt = 0; mt < 2; mt++) {
            int rowA = wm * 32 + mt * 16 + ((m & 1) << 3) + r;
            aOff[mt] = (uint32_t)rowA * ASTRIDE + (uint32_t)((m >> 1) << 4);
        }
        int q = lane >> 3;
        #pragma unroll
        for (int g = 0; g < 2; g++) {
            int nt  = g * 2 + (q >> 1);
            int col = wn * 16 + ((nt & 1) << 3) + ((nt >> 1) << 6);
            bAddr[g] = smemW32 + (uint32_t)(col + r) * ASTRIDE + (uint32_t)((q & 1) << 4);
        }
    }

    prefetchA(bid, smemBase, tid);
    if (n > 1) prefetchA(bid + GRID_GEMM, smemBase + ATILE, tid);

    for (int t = 0; t < n; t++) {
        if (t + 1 < n) { CP_WAIT(1); }
        else           { CP_WAIT(0); }
        __syncthreads();

        uint32_t aBuf = smemBase + (uint32_t)(t & 1) * ATILE;

        float acc[2][4][4];
        #pragma unroll
        for (int mt = 0; mt < 2; mt++)
            #pragma unroll
            for (int nt = 0; nt < 4; nt++)
                #pragma unroll
                for (int q = 0; q < 4; q++) acc[mt][nt][q] = 0.f;

        #pragma unroll
        for (int ks = 0; ks < 8; ks++) {
            uint32_t kkb = (uint32_t)ks * 32u;
            uint32_t a[2][4], B[2][4];
            ldsm_x4(a[0], aBuf + aOff[0] + kkb);
            ldsm_x4(a[1], aBuf + aOff[1] + kkb);
            ldsm_x4(B[0], bAddr[0] + kkb);
            ldsm_x4(B[1], bAddr[1] + kkb);
            #pragma unroll
            for (int nt = 0; nt < 4; nt++) {
                uint32_t b0 = B[nt >> 1][(nt & 1) * 2];
                uint32_t b1 = B[nt >> 1][(nt & 1) * 2 + 1];
                mma_fp16(acc[0][nt], a[0], b0, b1);
                mma_fp16(acc[1][nt], a[1], b0, b1);
            }
        }
        __syncthreads();
        if (t + 2 < n)
            prefetchA(bid + (t + 2) * GRID_GEMM, smemBase + (uint32_t)(t & 1) * ATILE, tid);

        // register epilogue: act + projection
        int rA = lane >> 2;
        int cA = (lane & 3) * 2;
        float s0[2], s1[2];
        #pragma unroll
        for (int mt = 0; mt < 2; mt++) { s0[mt] = 0.f; s1[mt] = 0.f; }
        #pragma unroll
        for (int mt = 0; mt < 2; mt++) {
            #pragma unroll
            for (int ntc = 0; ntc < 2; ntc++) {
                const float* aZ = acc[mt][ntc];
                const float* aH = acc[mt][ntc + 2];
                int cbase = wn * 16 + ntc * 8 + cA;
                #pragma unroll
                for (int u = 0; u < 2; u++) {
                    int c = cbase + u;
                    float bz = sBZ[c], bh = sBH[c], w = sWl[c];
                    {
                        float A = aZ[u] + bz, Bv = aH[u] + bh;
                        float z  = __fdividef(1.f, 1.f + __expf(-A));
                        float e2 = __expf(2.f * Bv);
                        float th = 1.f - __fdividef(2.f, e2 + 1.f);
                        s0[mt] = fmaf(fmaxf((1.f - z) * th, 0.f), w, s0[mt]);
                    }
                    {
                        float A = aZ[2 + u] + bz, Bv = aH[2 + u] + bh;
                        float z  = __fdividef(1.f, 1.f + __expf(-A));
                        float e2 = __expf(2.f * Bv);
                        float th = 1.f - __fdividef(2.f, e2 + 1.f);
                        s1[mt] = fmaf(fmaxf((1.f - z) * th, 0.f), w, s1[mt]);
                    }
                }
            }
        }
        #pragma unroll
        for (int mt = 0; mt < 2; mt++) {
            s0[mt] += __shfl_xor_sync(0xffffffffu, s0[mt], 1);
            s0[mt] += __shfl_xor_sync(0xffffffffu, s0[mt], 2);
            s1[mt] += __shfl_xor_sync(0xffffffffu, s1[mt], 1);
            s1[mt] += __shfl_xor_sync(0xffffffffu, s1[mt], 2);
        }
        if ((lane & 3) == 0) {
            #pragma unroll
            for (int mt = 0; mt < 2; mt++) {
                int r = wm * 32 + mt * 16 + rA;
                sRed[r][wn]     = s0[mt];
                sRed[r + 8][wn] = s1[mt];
            }
        }
        __syncthreads();
        if (tid < 128) {
            float v = sRed[tid][0] + sRed[tid][1] + sRed[tid][2] + sRed[tid][3];
            int rg   = (bid + t * GRID_GEMM) * 128 + tid;   // row' = node*8 + tt
            int node = rg >> 3;
            int tt   = rg & 7;
            out[tt * N_NODES + node] = v + blin0;
        }
    }
}

// ---------------- launch ----------------
extern "C" void kernel_launch(void* const* d_in, const int* in_sizes, int n_in,
                              void* d_out, int out_size)
{
    const float* x    = (const float*)d_in[0];
    const int*   ei   = (const int*)  d_in[1];
    const float* ew   = (const float*)d_in[2];
    const float* Wxz0 = (const float*)d_in[3];
    const float* Wxz1 = (const float*)d_in[4];
    const float* bxz  = (const float*)d_in[5];
    const float* bhz  = (const float*)d_in[8];
    const float* Wxh0 = (const float*)d_in[15];
    const float* Wxh1 = (const float*)d_in[16];
    const float* bxh  = (const float*)d_in[17];
    const float* bhh  = (const float*)d_in[20];
    const float* Wlin = (const float*)d_in[21];
    const float* blin = (const float*)d_in[22];
    float* out = (float*)d_out;

    cudaFuncSetAttribute(k_gemm, cudaFuncAttributeMaxDynamicSharedMemorySize, DSMEM_BYTES);

    const int NB_E = (E_EDGES + 255) / 256;
    const int NB_C = (XCHUNKS + 255) / 256;    // 12500 blocks

    k_prep0  <<<NB_C, 256>>>((const float4*)x, ei, ew);  // 1: transpose (16B chunks) + deg
    k_fill   <<<NB_E, 256>>>(ei, ew);                    // 2: bucket fill
    k_gather <<<(N_NODES * 32 + 255) / 256, 256>>>();    // 3: 1 warp/node (R8 winner)
    k_gemm   <<<GRID_GEMM, GTHREADS, DSMEM_BYTES>>>(Wxz0, Wxz1, Wxh0, Wxh1,
                                                    bxz, bhz, bxh, bhh, Wlin, blin, out);
}

// round 14
// speedup vs baseline: 1.3058x; 1.1005x over previous
#include <cuda_runtime.h>
#include <cuda_fp16.h>
#include <cstdint>
#include <cstddef>

#define T_DIM   8
#define N_NODES 50000
#define E_EDGES 800000
#define C_DIM   64
#define M_ROWS  (T_DIM * N_NODES)   // 400000 rows of [x | tx1]
#define BCAP    64                   // bucket capacity per node (P(deg>64) ~ 0)

// ---------------- scratch (static device globals; no allocation) ----------------
// g_deg / g_cnt are zeroed by k_gemm at the END of each invocation (and are
// zero at module load), so the prep path needs no separate zeroing kernel.
__device__ float   g_deg[N_NODES];
__device__ int     g_cnt[N_NODES];
__device__ uint2   g_cv[(size_t)N_NODES * BCAP];        // packed (col,val) buckets
// node-major fp16: [node][t][32 half2] — 1KB per node
__device__ __half2 g_xh  [(size_t)M_ROWS * (C_DIM/2)];  // 51.2 MB
__device__ __half2 g_tx1h[(size_t)M_ROWS * (C_DIM/2)];  // 51.2 MB

// ---------------- prep0: x -> fp16 node-major transpose (16B chunks, no IDIV)
//                  + deg atomics (fused) ----------------
#define XCHUNKS (M_ROWS * 8)   // 3.2M 16-byte output chunks

__global__ void k_prep0(const float4* __restrict__ x4,
                        const int* __restrict__ ei, const float* __restrict__ ew) {
    int j = blockIdx.x * blockDim.x + threadIdx.x;
    if (j < E_EDGES) {
        atomicAdd(&g_deg[ei[j]], ew[j]);     // g_deg pre-zeroed by prior k_gemm
    }
    if (j < XCHUNKS) {
        int c4 = j & 7;          // which 16B chunk within the 128B t-row
        int r  = j >> 3;         // node-major row = n*8 + t
        int n  = r >> 3;
        int t  = r & 7;
        size_t s = ((size_t)t * N_NODES + n) * 16 + (size_t)c4 * 2;
        float4 v0 = __ldg(&x4[s]);
        float4 v1 = __ldg(&x4[s + 1]);
        uint4 o;
        __half2 h;
        h = __floats2half2_rn(v0.x, v0.y); o.x = *(uint32_t*)&h;
        h = __floats2half2_rn(v0.z, v0.w); o.y = *(uint32_t*)&h;
        h = __floats2half2_rn(v1.x, v1.y); o.z = *(uint32_t*)&h;
        h = __floats2half2_rn(v1.z, v1.w); o.w = *(uint32_t*)&h;
        ((uint4*)g_xh)[j] = o;
    }
}

// ---------------- bucket fill: slot via atomic cnt, packed (col,val) STG.64 ----------------
__device__ __forceinline__ float dinv_of(float dg) {
    return (dg > 0.f) ? rsqrtf(fmaxf(dg, 1e-12f)) : 0.f;
}

__global__ void k_fill(const int* __restrict__ ei, const float* __restrict__ ew) {
    int e = blockIdx.x * blockDim.x + threadIdx.x;
    if (e < E_EDGES) {
        int s = ei[e];
        int d = ei[E_EDGES + e];
        float nw = -ew[e] * dinv_of(g_deg[s]) * dinv_of(g_deg[d]);
        int p = atomicAdd(&g_cnt[d], 1);   // g_cnt pre-zeroed by prior k_gemm
        if (p < BCAP) {
            uint2 cv;
            cv.x = (uint32_t)s;
            cv.y = __float_as_uint(nw);
            g_cv[((size_t)d << 6) + p] = cv;
        }
    }
}

// ---------------- gather (R8 winner): one warp per dst node, lane owns 32B slice ----------------
__global__ void k_gather() {
    int warp = (blockIdx.x * blockDim.x + threadIdx.x) >> 5;
    int lane = threadIdx.x & 31;
    if (warp >= N_NODES) return;
    int cnt = g_cnt[warp];
    if (cnt > BCAP) cnt = BCAP;
    const uint2* __restrict__ bucket = g_cv + ((size_t)warp << 6);

    float2 acc[8];
    #pragma unroll
    for (int q = 0; q < 8; q++) acc[q] = make_float2(0.f, 0.f);

    const char* xbase = (const char*)g_xh + (size_t)lane * 32;

    int e = 0;
    for (; e + 1 < cnt; e += 2) {
        uint2 cv0 = __ldg(&bucket[e]);
        uint2 cv1 = __ldg(&bucket[e + 1]);
        float v0 = __uint_as_float(cv0.y);
        float v1 = __uint_as_float(cv1.y);
        const uint4* p0 = (const uint4*)(xbase + (size_t)cv0.x * 1024);
        const uint4* p1 = (const uint4*)(xbase + (size_t)cv1.x * 1024);
        uint4 a0 = __ldg(p0), b0 = __ldg(p0 + 1);
        uint4 a1 = __ldg(p1), b1 = __ldg(p1 + 1);
        const uint32_t* w0 = (const uint32_t*)&a0;
        const uint32_t* u0 = (const uint32_t*)&b0;
        const uint32_t* w1 = (const uint32_t*)&a1;
        const uint32_t* u1 = (const uint32_t*)&b1;
        #pragma unroll
        for (int q = 0; q < 4; q++) {
            float2 f;
            f = __half22float2(*(const __half2*)&w0[q]);
            acc[q].x = fmaf(v0, f.x, acc[q].x); acc[q].y = fmaf(v0, f.y, acc[q].y);
            f = __half22float2(*(const __half2*)&u0[q]);
            acc[4+q].x = fmaf(v0, f.x, acc[4+q].x); acc[4+q].y = fmaf(v0, f.y, acc[4+q].y);
            f = __half22float2(*(const __half2*)&w1[q]);
            acc[q].x = fmaf(v1, f.x, acc[q].x); acc[q].y = fmaf(v1, f.y, acc[q].y);
            f = __half22float2(*(const __half2*)&u1[q]);
            acc[4+q].x = fmaf(v1, f.x, acc[4+q].x); acc[4+q].y = fmaf(v1, f.y, acc[4+q].y);
        }
    }
    if (e < cnt) {
        uint2 cv0 = __ldg(&bucket[e]);
        float v0 = __uint_as_float(cv0.y);
        const uint4* p0 = (const uint4*)(xbase + (size_t)cv0.x * 1024);
        uint4 a0 = __ldg(p0), b0 = __ldg(p0 + 1);
        const uint32_t* w0 = (const uint32_t*)&a0;
        const uint32_t* u0 = (const uint32_t*)&b0;
        #pragma unroll
        for (int q = 0; q < 4; q++) {
            float2 f;
            f = __half22float2(*(const __half2*)&w0[q]);
            acc[q].x = fmaf(v0, f.x, acc[q].x); acc[q].y = fmaf(v0, f.y, acc[q].y);
            f = __half22float2(*(const __half2*)&u0[q]);
            acc[4+q].x = fmaf(v0, f.x, acc[4+q].x); acc[4+q].y = fmaf(v0, f.y, acc[4+q].y);
        }
    }

    uint4 o0, o1;
    uint32_t* w = (uint32_t*)&o0;
    uint32_t* u = (uint32_t*)&o1;
    #pragma unroll
    for (int q = 0; q < 4; q++) {
        __half2 h0 = __floats2half2_rn(acc[q].x, acc[q].y);
        __half2 h1 = __floats2half2_rn(acc[4+q].x, acc[4+q].y);
        w[q] = *(uint32_t*)&h0;
        u[q] = *(uint32_t*)&h1;
    }
    uint4* op = (uint4*)((char*)g_tx1h + (size_t)warp * 1024 + (size_t)lane * 32);
    op[0] = o0;
    op[1] = o1;
}

// ============================================================================
// HMMA fp16 GEMM — 2 CTAs/SM: grid 296, 256 threads, 64x128 tile, warp = 32x32,
// ldmatrix frags, 2-stage cp.async, tanh.approx epilogue.
// Zeroes g_cnt/g_deg for next invocation.
// ============================================================================

#define TILE_ROWS 64
#define TILES     (M_ROWS / TILE_ROWS)   // 6250
#define GRID_GEMM 296
#define GTHREADS  256

#define ASTRIDE 272u
#define ATILE   ((uint32_t)TILE_ROWS * ASTRIDE)   // 17408
#define NBUF    2
#define OFF_W   (NBUF * ATILE)
#define WTILE   (128u * ASTRIDE)                  // 34816 (W is 128x128)
#define DSMEM_BYTES (NBUF * ATILE + WTILE)        // 69632

#define CP_ASYNC16(dst, src) \
    asm volatile("cp.async.cg.shared.global [%0], [%1], 16;" :: "r"(dst), "l"(src))
#define CP_COMMIT() asm volatile("cp.async.commit_group;" ::: "memory")
#define CP_WAIT(n)  asm volatile("cp.async.wait_group %0;" :: "n"(n) : "memory")

__device__ __forceinline__ void mma_fp16(float* c, const uint32_t* a,
                                         uint32_t b0, uint32_t b1) {
    asm volatile(
        "mma.sync.aligned.m16n8k16.row.col.f32.f16.f16.f32 "
        "{%0,%1,%2,%3}, {%4,%5,%6,%7}, {%8,%9}, {%0,%1,%2,%3};"
        : "+f"(c[0]), "+f"(c[1]), "+f"(c[2]), "+f"(c[3])
        : "r"(a[0]), "r"(a[1]), "r"(a[2]), "r"(a[3]), "r"(b0), "r"(b1));
}

__device__ __forceinline__ void ldsm_x4(uint32_t* d, uint32_t addr) {
    asm volatile("ldmatrix.sync.aligned.m8n8.x4.shared.b16 {%0,%1,%2,%3}, [%4];"
                 : "=r"(d[0]), "=r"(d[1]), "=r"(d[2]), "=r"(d[3]) : "r"(addr));
}

__device__ __forceinline__ float tanh_fast(float x) {
    float r;
    asm("tanh.approx.f32 %0, %1;" : "=f"(r) : "f"(x));
    return r;
}

__device__ __forceinline__ void prefetchA(int tile, uint32_t dstBase, int tid) {
    int rowBase = tile * TILE_ROWS;
    #pragma unroll
    for (int it = 0; it < 4; it++) {
        int chunk = tid + it * GTHREADS;   // 0..1023 chunks of 16B (64 rows x 16)
        int r   = chunk >> 4;
        int c16 = chunk & 15;
        size_t row = (size_t)(rowBase + r);
        const void* src = (c16 < 8)
            ? (const void*)(g_xh   + row * 32 + c16 * 4)
            : (const void*)(g_tx1h + row * 32 + (c16 - 8) * 4);
        uint32_t dst = dstBase + (uint32_t)r * ASTRIDE + (uint32_t)c16 * 16u;
        CP_ASYNC16(dst, src);
    }
    CP_COMMIT();
}

__global__ void __launch_bounds__(GTHREADS, 2) k_gemm(
    const float* __restrict__ Wxz0, const float* __restrict__ Wxz1,
    const float* __restrict__ Wxh0, const float* __restrict__ Wxh1,
    const float* __restrict__ bxz,  const float* __restrict__ bhz,
    const float* __restrict__ bxh,  const float* __restrict__ bhh,
    const float* __restrict__ wlin, const float* __restrict__ blin,
    float* __restrict__ out)
{
    extern __shared__ char dsm[];
    __shared__ float sBZ[64], sBH[64], sWl[64];
    __shared__ float sRed[TILE_ROWS][4];

    char* WTh = dsm + OFF_W;
    uint32_t smemBase = (uint32_t)__cvta_generic_to_shared(dsm);
    uint32_t smemW32  = smemBase + OFF_W;

    int tid  = threadIdx.x;
    int wid  = tid >> 5;
    int lane = tid & 31;
    int bid  = blockIdx.x;
    int n = (TILES - bid + GRID_GEMM - 1) / GRID_GEMM;

    // zero cnt/deg for the NEXT kernel_launch invocation
    for (int i = bid * GTHREADS + tid; i < N_NODES; i += GRID_GEMM * GTHREADS) {
        g_cnt[i] = 0;
        g_deg[i] = 0.f;
    }

    int wm = wid >> 2;           // 0..1 : rows wm*32 ..
    int wn = wid & 3;            // 0..3 : Z cols wn*16.., H cols 64+wn*16..

    for (int idx = tid; idx < 16384; idx += GTHREADS) {
        int nn = idx >> 7;
        int k  = idx & 127;
        float v;
        if (k < 64) v = (nn < 64) ? Wxz0[k * 64 + nn]        : Wxh0[k * 64 + (nn - 64)];
        else        v = (nn < 64) ? Wxz1[(k - 64) * 64 + nn] : Wxh1[(k - 64) * 64 + (nn - 64)];
        *(__half*)(WTh + (uint32_t)nn * ASTRIDE + (uint32_t)k * 2u) = __float2half_rn(v);
    }
    if (tid < 64) {
        sBZ[tid] = bxz[tid] + bhz[tid];
        sBH[tid] = bxh[tid] + bhh[tid];
        sWl[tid] = wlin[tid];
    }
    float blin0 = blin[0];

    // ldmatrix per-lane addresses
    uint32_t aOff[2];   // relative to A-buffer base
    uint32_t bAddr[2];  // absolute (W tile fixed)
    {
        int m = lane >> 3, r = lane & 7;
        #pragma unroll
        for (int mt = 0; mt < 2; mt++) {
            int rowA = wm * 32 + mt * 16 + ((m & 1) << 3) + r;
            aOff[mt] = (uint32_t)rowA * ASTRIDE + (uint32_t)((m >> 1) << 4);
        }
        int q = lane >> 3;
        #pragma unroll
        for (int g = 0; g < 2; g++) {
            int nt  = g * 2 + (q >> 1);
            int col = wn * 16 + ((nt & 1) << 3) + ((nt >> 1) << 6);
            bAddr[g] = smemW32 + (uint32_t)(col + r) * ASTRIDE + (uint32_t)((q & 1) << 4);
        }
    }

    prefetchA(bid, smemBase, tid);
    if (n > 1) prefetchA(bid + GRID_GEMM, smemBase + ATILE, tid);

    for (int t = 0; t < n; t++) {
        if (t + 1 < n) { CP_WAIT(1); }
        else           { CP_WAIT(0); }
        __syncthreads();

        uint32_t aBuf = smemBase + (uint32_t)(t & 1) * ATILE;

        float acc[2][4][4];
        #pragma unroll
        for (int mt = 0; mt < 2; mt++)
            #pragma unroll
            for (int nt = 0; nt < 4; nt++)
                #pragma unroll
                for (int q = 0; q < 4; q++) acc[mt][nt][q] = 0.f;

        #pragma unroll
        for (int ks = 0; ks < 8; ks++) {
            uint32_t kkb = (uint32_t)ks * 32u;
            uint32_t a[2][4], B[2][4];
            ldsm_x4(a[0], aBuf + aOff[0] + kkb);
            ldsm_x4(a[1], aBuf + aOff[1] + kkb);
            ldsm_x4(B[0], bAddr[0] + kkb);
            ldsm_x4(B[1], bAddr[1] + kkb);
            #pragma unroll
            for (int nt = 0; nt < 4; nt++) {
                uint32_t b0 = B[nt >> 1][(nt & 1) * 2];
                uint32_t b1 = B[nt >> 1][(nt & 1) * 2 + 1];
                mma_fp16(acc[0][nt], a[0], b0, b1);
                mma_fp16(acc[1][nt], a[1], b0, b1);
            }
        }
        __syncthreads();
        if (t + 2 < n)
            prefetchA(bid + (t + 2) * GRID_GEMM, smemBase + (uint32_t)(t & 1) * ATILE, tid);

        // register epilogue (tanh.approx): z = 0.5+0.5*ta, (1-z)*th = 0.5*(1-ta)*th
        int rA = lane >> 2;
        int cA = (lane & 3) * 2;
        float s0[2], s1[2];
        #pragma unroll
        for (int mt = 0; mt < 2; mt++) { s0[mt] = 0.f; s1[mt] = 0.f; }
        #pragma unroll
        for (int mt = 0; mt < 2; mt++) {
            #pragma unroll
            for (int ntc = 0; ntc < 2; ntc++) {
                const float* aZ = acc[mt][ntc];
                const float* aH = acc[mt][ntc + 2];
                int cbase = wn * 16 + ntc * 8 + cA;
                #pragma unroll
                for (int u = 0; u < 2; u++) {
                    int c = cbase + u;
                    float bz = sBZ[c], bh = sBH[c], w = sWl[c];
                    {
                        float ta = tanh_fast((aZ[u] + bz) * 0.5f);
                        float th = tanh_fast(aH[u] + bh);
                        float h  = fmaxf(0.5f * (1.f - ta) * th, 0.f);
                        s0[mt] = fmaf(h, w, s0[mt]);
                    }
                    {
                        float ta = tanh_fast((aZ[2 + u] + bz) * 0.5f);
                        float th = tanh_fast(aH[2 + u] + bh);
                        float h  = fmaxf(0.5f * (1.f - ta) * th, 0.f);
                        s1[mt] = fmaf(h, w, s1[mt]);
                    }
                }
            }
        }
        #pragma unroll
        for (int mt = 0; mt < 2; mt++) {
            s0[mt] += __shfl_xor_sync(0xffffffffu, s0[mt], 1);
            s0[mt] += __shfl_xor_sync(0xffffffffu, s0[mt], 2);
            s1[mt] += __shfl_xor_sync(0xffffffffu, s1[mt], 1);
            s1[mt] += __shfl_xor_sync(0xffffffffu, s1[mt], 2);
        }
        if ((lane & 3) == 0) {
            #pragma unroll
            for (int mt = 0; mt < 2; mt++) {
                int r = wm * 32 + mt * 16 + rA;
                sRed[r][wn]     = s0[mt];
                sRed[r + 8][wn] = s1[mt];
            }
        }
        __syncthreads();
        if (tid < TILE_ROWS) {
            float v = sRed[tid][0] + sRed[tid][1] + sRed[tid][2] + sRed[tid][3];
            int rg   = (bid + t * GRID_GEMM) * TILE_ROWS + tid;   // row' = node*8 + tt
            int node = rg >> 3;
            int tt   = rg & 7;
            out[tt * N_NODES + node] = v + blin0;
        }
    }
}

// ---------------- launch ----------------
extern "C" void kernel_launch(void* const* d_in, const int* in_sizes, int n_in,
                              void* d_out, int out_size)
{
    const float* x    = (const float*)d_in[0];
    const int*   ei   = (const int*)  d_in[1];
    const float* ew   = (const float*)d_in[2];
    const float* Wxz0 = (const float*)d_in[3];
    const float* Wxz1 = (const float*)d_in[4];
    const float* bxz  = (const float*)d_in[5];
    const float* bhz  = (const float*)d_in[8];
    const float* Wxh0 = (const float*)d_in[15];
    const float* Wxh1 = (const float*)d_in[16];
    const float* bxh  = (const float*)d_in[17];
    const float* bhh  = (const float*)d_in[20];
    const float* Wlin = (const float*)d_in[21];
    const float* blin = (const float*)d_in[22];
    float* out = (float*)d_out;

    cudaFuncSetAttribute(k_gemm, cudaFuncAttributeMaxDynamicSharedMemorySize, DSMEM_BYTES);

    const int NB_E = (E_EDGES + 255) / 256;
    const int NB_C = (XCHUNKS + 255) / 256;    // 12500 blocks

    k_prep0  <<<NB_C, 256>>>((const float4*)x, ei, ew);  // 1: transpose (16B chunks) + deg
    k_fill   <<<NB_E, 256>>>(ei, ew);                    // 2: bucket fill
    k_gather <<<(N_NODES * 32 + 255) / 256, 256>>>();    // 3: 1 warp/node (R8 winner)
    k_gemm   <<<GRID_GEMM, GTHREADS, DSMEM_BYTES>>>(Wxz0, Wxz1, Wxh0, Wxh1,
                                                    bxz, bhz, bxh, bhh, Wlin, blin, out);
}

// round 15
// speedup vs baseline: 1.3216x; 1.0121x over previous
#include <cuda_runtime.h>
#include <cuda_fp16.h>
#include <cstdint>
#include <cstddef>

#define T_DIM   8
#define N_NODES 50000
#define E_EDGES 800000
#define C_DIM   64
#define M_ROWS  (T_DIM * N_NODES)   // 400000 rows of [x | tx1]
#define BCAP    64                   // bucket capacity per node (P(deg>64) ~ 0)

// ---------------- scratch (static device globals; no allocation) ----------------
// g_deg / g_cnt are zeroed by k_gemm at the END of each invocation (and are
// zero at module load), so the prep path needs no separate zeroing kernel.
__device__ float   g_deg[N_NODES];
__device__ int     g_cnt[N_NODES];
__device__ uint2   g_cv[(size_t)N_NODES * BCAP];        // packed (src, raw ew) buckets
// node-major fp16: [node][t][32 half2] — 1KB per node
__device__ __half2 g_xh  [(size_t)M_ROWS * (C_DIM/2)];  // 51.2 MB
__device__ __half2 g_tx1h[(size_t)M_ROWS * (C_DIM/2)];  // 51.2 MB

// ---------------- prep0: x->fp16 node-major transpose + deg atomics + bucket fill
//                  (single pass over the edge stream; buckets hold RAW ew) ----------------
#define XCHUNKS (M_ROWS * 8)   // 3.2M 16-byte output chunks

__global__ void k_prep0(const float4* __restrict__ x4,
                        const int* __restrict__ ei, const float* __restrict__ ew) {
    int j = blockIdx.x * blockDim.x + threadIdx.x;
    if (j < E_EDGES) {
        int s = ei[j];
        int d = ei[E_EDGES + j];
        float w = ew[j];
        atomicAdd(&g_deg[s], w);            // g_deg pre-zeroed by prior k_gemm
        int p = atomicAdd(&g_cnt[d], 1);    // g_cnt pre-zeroed by prior k_gemm
        if (p < BCAP) {
            uint2 cv;
            cv.x = (uint32_t)s;
            cv.y = __float_as_uint(w);      // raw weight; normalized in gather
            g_cv[((size_t)d << 6) + p] = cv;
        }
    }
    if (j < XCHUNKS) {
        int c4 = j & 7;          // which 16B chunk within the 128B t-row
        int r  = j >> 3;         // node-major row = n*8 + t
        int n  = r >> 3;
        int t  = r & 7;
        size_t s = ((size_t)t * N_NODES + n) * 16 + (size_t)c4 * 2;
        float4 v0 = __ldg(&x4[s]);
        float4 v1 = __ldg(&x4[s + 1]);
        uint4 o;
        __half2 h;
        h = __floats2half2_rn(v0.x, v0.y); o.x = *(uint32_t*)&h;
        h = __floats2half2_rn(v0.z, v0.w); o.y = *(uint32_t*)&h;
        h = __floats2half2_rn(v1.x, v1.y); o.z = *(uint32_t*)&h;
        h = __floats2half2_rn(v1.z, v1.w); o.w = *(uint32_t*)&h;
        ((uint4*)g_xh)[j] = o;
    }
}

// ---------------- gather: one warp per dst node, lane owns 32B slice;
//                  nw computed on the fly (dinv hidden under L2 latency) ----------------
__device__ __forceinline__ float dinv_of(float dg) {
    return (dg > 0.f) ? rsqrtf(fmaxf(dg, 1e-12f)) : 0.f;
}

__global__ void k_gather() {
    int warp = (blockIdx.x * blockDim.x + threadIdx.x) >> 5;
    int lane = threadIdx.x & 31;
    if (warp >= N_NODES) return;
    int cnt = 0;
    float dinvD = 0.f;
    if (lane == 0) {
        cnt = g_cnt[warp];
        dinvD = dinv_of(g_deg[warp]);
    }
    cnt   = __shfl_sync(0xffffffffu, cnt, 0);
    dinvD = __shfl_sync(0xffffffffu, dinvD, 0);
    if (cnt > BCAP) cnt = BCAP;
    const uint2* __restrict__ bucket = g_cv + ((size_t)warp << 6);

    float2 acc[8];
    #pragma unroll
    for (int q = 0; q < 8; q++) acc[q] = make_float2(0.f, 0.f);

    const char* xbase = (const char*)g_xh + (size_t)lane * 32;

    int e = 0;
    for (; e + 1 < cnt; e += 2) {
        uint2 cv0 = __ldg(&bucket[e]);
        uint2 cv1 = __ldg(&bucket[e + 1]);
        float v0 = -__uint_as_float(cv0.y) * dinv_of(__ldg(&g_deg[cv0.x])) * dinvD;
        float v1 = -__uint_as_float(cv1.y) * dinv_of(__ldg(&g_deg[cv1.x])) * dinvD;
        const uint4* p0 = (const uint4*)(xbase + (size_t)cv0.x * 1024);
        const uint4* p1 = (const uint4*)(xbase + (size_t)cv1.x * 1024);
        uint4 a0 = __ldg(p0), b0 = __ldg(p0 + 1);
        uint4 a1 = __ldg(p1), b1 = __ldg(p1 + 1);
        const uint32_t* w0 = (const uint32_t*)&a0;
        const uint32_t* u0 = (const uint32_t*)&b0;
        const uint32_t* w1 = (const uint32_t*)&a1;
        const uint32_t* u1 = (const uint32_t*)&b1;
        #pragma unroll
        for (int q = 0; q < 4; q++) {
            float2 f;
            f = __half22float2(*(const __half2*)&w0[q]);
            acc[q].x = fmaf(v0, f.x, acc[q].x); acc[q].y = fmaf(v0, f.y, acc[q].y);
            f = __half22float2(*(const __half2*)&u0[q]);
            acc[4+q].x = fmaf(v0, f.x, acc[4+q].x); acc[4+q].y = fmaf(v0, f.y, acc[4+q].y);
            f = __half22float2(*(const __half2*)&w1[q]);
            acc[q].x = fmaf(v1, f.x, acc[q].x); acc[q].y = fmaf(v1, f.y, acc[q].y);
            f = __half22float2(*(const __half2*)&u1[q]);
            acc[4+q].x = fmaf(v1, f.x, acc[4+q].x); acc[4+q].y = fmaf(v1, f.y, acc[4+q].y);
        }
    }
    if (e < cnt) {
        uint2 cv0 = __ldg(&bucket[e]);
        float v0 = -__uint_as_float(cv0.y) * dinv_of(__ldg(&g_deg[cv0.x])) * dinvD;
        const uint4* p0 = (const uint4*)(xbase + (size_t)cv0.x * 1024);
        uint4 a0 = __ldg(p0), b0 = __ldg(p0 + 1);
        const uint32_t* w0 = (const uint32_t*)&a0;
        const uint32_t* u0 = (const uint32_t*)&b0;
        #pragma unroll
        for (int q = 0; q < 4; q++) {
            float2 f;
            f = __half22float2(*(const __half2*)&w0[q]);
            acc[q].x = fmaf(v0, f.x, acc[q].x); acc[q].y = fmaf(v0, f.y, acc[q].y);
            f = __half22float2(*(const __half2*)&u0[q]);
            acc[4+q].x = fmaf(v0, f.x, acc[4+q].x); acc[4+q].y = fmaf(v0, f.y, acc[4+q].y);
        }
    }

    uint4 o0, o1;
    uint32_t* w = (uint32_t*)&o0;
    uint32_t* u = (uint32_t*)&o1;
    #pragma unroll
    for (int q = 0; q < 4; q++) {
        __half2 h0 = __floats2half2_rn(acc[q].x, acc[q].y);
        __half2 h1 = __floats2half2_rn(acc[4+q].x, acc[4+q].y);
        w[q] = *(uint32_t*)&h0;
        u[q] = *(uint32_t*)&h1;
    }
    uint4* op = (uint4*)((char*)g_tx1h + (size_t)warp * 1024 + (size_t)lane * 32);
    op[0] = o0;
    op[1] = o1;
}

// ============================================================================
// HMMA fp16 GEMM — 2 CTAs/SM: grid 296, 256 threads, 64x128 tile, warp = 32x32,
// ldmatrix frags, 2-stage cp.async, tanh.approx epilogue.
// Zeroes g_cnt/g_deg for next invocation.
// ============================================================================

#define TILE_ROWS 64
#define TILES     (M_ROWS / TILE_ROWS)   // 6250
#define GRID_GEMM 296
#define GTHREADS  256

#define ASTRIDE 272u
#define ATILE   ((uint32_t)TILE_ROWS * ASTRIDE)   // 17408
#define NBUF    2
#define OFF_W   (NBUF * ATILE)
#define WTILE   (128u * ASTRIDE)                  // 34816 (W is 128x128)
#define DSMEM_BYTES (NBUF * ATILE + WTILE)        // 69632

#define CP_ASYNC16(dst, src) \
    asm volatile("cp.async.cg.shared.global [%0], [%1], 16;" :: "r"(dst), "l"(src))
#define CP_COMMIT() asm volatile("cp.async.commit_group;" ::: "memory")
#define CP_WAIT(n)  asm volatile("cp.async.wait_group %0;" :: "n"(n) : "memory")

__device__ __forceinline__ void mma_fp16(float* c, const uint32_t* a,
                                         uint32_t b0, uint32_t b1) {
    asm volatile(
        "mma.sync.aligned.m16n8k16.row.col.f32.f16.f16.f32 "
        "{%0,%1,%2,%3}, {%4,%5,%6,%7}, {%8,%9}, {%0,%1,%2,%3};"
        : "+f"(c[0]), "+f"(c[1]), "+f"(c[2]), "+f"(c[3])
        : "r"(a[0]), "r"(a[1]), "r"(a[2]), "r"(a[3]), "r"(b0), "r"(b1));
}

__device__ __forceinline__ void ldsm_x4(uint32_t* d, uint32_t addr) {
    asm volatile("ldmatrix.sync.aligned.m8n8.x4.shared.b16 {%0,%1,%2,%3}, [%4];"
                 : "=r"(d[0]), "=r"(d[1]), "=r"(d[2]), "=r"(d[3]) : "r"(addr));
}

__device__ __forceinline__ float tanh_fast(float x) {
    float r;
    asm("tanh.approx.f32 %0, %1;" : "=f"(r) : "f"(x));
    return r;
}

__device__ __forceinline__ void prefetchA(int tile, uint32_t dstBase, int tid) {
    int rowBase = tile * TILE_ROWS;
    #pragma unroll
    for (int it = 0; it < 4; it++) {
        int chunk = tid + it * GTHREADS;   // 0..1023 chunks of 16B (64 rows x 16)
        int r   = chunk >> 4;
        int c16 = chunk & 15;
        size_t row = (size_t)(rowBase + r);
        const void* src = (c16 < 8)
            ? (const void*)(g_xh   + row * 32 + c16 * 4)
            : (const void*)(g_tx1h + row * 32 + (c16 - 8) * 4);
        uint32_t dst = dstBase + (uint32_t)r * ASTRIDE + (uint32_t)c16 * 16u;
        CP_ASYNC16(dst, src);
    }
    CP_COMMIT();
}

__global__ void __launch_bounds__(GTHREADS, 2) k_gemm(
    const float* __restrict__ Wxz0, const float* __restrict__ Wxz1,
    const float* __restrict__ Wxh0, const float* __restrict__ Wxh1,
    const float* __restrict__ bxz,  const float* __restrict__ bhz,
    const float* __restrict__ bxh,  const float* __restrict__ bhh,
    const float* __restrict__ wlin, const float* __restrict__ blin,
    float* __restrict__ out)
{
    extern __shared__ char dsm[];
    __shared__ float sBZ[64], sBH[64], sWl[64];
    __shared__ float sRed[TILE_ROWS][4];

    char* WTh = dsm + OFF_W;
    uint32_t smemBase = (uint32_t)__cvta_generic_to_shared(dsm);
    uint32_t smemW32  = smemBase + OFF_W;

    int tid  = threadIdx.x;
    int wid  = tid >> 5;
    int lane = tid & 31;
    int bid  = blockIdx.x;
    int n = (TILES - bid + GRID_GEMM - 1) / GRID_GEMM;

    // zero cnt/deg for the NEXT kernel_launch invocation
    for (int i = bid * GTHREADS + tid; i < N_NODES; i += GRID_GEMM * GTHREADS) {
        g_cnt[i] = 0;
        g_deg[i] = 0.f;
    }

    int wm = wid >> 2;           // 0..1 : rows wm*32 ..
    int wn = wid & 3;            // 0..3 : Z cols wn*16.., H cols 64+wn*16..

    for (int idx = tid; idx < 16384; idx += GTHREADS) {
        int nn = idx >> 7;
        int k  = idx & 127;
        float v;
        if (k < 64) v = (nn < 64) ? Wxz0[k * 64 + nn]        : Wxh0[k * 64 + (nn - 64)];
        else        v = (nn < 64) ? Wxz1[(k - 64) * 64 + nn] : Wxh1[(k - 64) * 64 + (nn - 64)];
        *(__half*)(WTh + (uint32_t)nn * ASTRIDE + (uint32_t)k * 2u) = __float2half_rn(v);
    }
    if (tid < 64) {
        sBZ[tid] = bxz[tid] + bhz[tid];
        sBH[tid] = bxh[tid] + bhh[tid];
        sWl[tid] = wlin[tid];
    }
    float blin0 = blin[0];

    // ldmatrix per-lane addresses
    uint32_t aOff[2];   // relative to A-buffer base
    uint32_t bAddr[2];  // absolute (W tile fixed)
    {
        int m = lane >> 3, r = lane & 7;
        #pragma unroll
        for (int mt = 0; mt < 2; mt++) {
            int rowA = wm * 32 + mt * 16 + ((m & 1) << 3) + r;
            aOff[mt] = (uint32_t)rowA * ASTRIDE + (uint32_t)((m >> 1) << 4);
        }
        int q = lane >> 3;
        #pragma unroll
        for (int g = 0; g < 2; g++) {
            int nt  = g * 2 + (q >> 1);
            int col = wn * 16 + ((nt & 1) << 3) + ((nt >> 1) << 6);
            bAddr[g] = smemW32 + (uint32_t)(col + r) * ASTRIDE + (uint32_t)((q & 1) << 4);
        }
    }

    prefetchA(bid, smemBase, tid);
    if (n > 1) prefetchA(bid + GRID_GEMM, smemBase + ATILE, tid);

    for (int t = 0; t < n; t++) {
        if (t + 1 < n) { CP_WAIT(1); }
        else           { CP_WAIT(0); }
        __syncthreads();

        uint32_t aBuf = smemBase + (uint32_t)(t & 1) * ATILE;

        float acc[2][4][4];
        #pragma unroll
        for (int mt = 0; mt < 2; mt++)
            #pragma unroll
            for (int nt = 0; nt < 4; nt++)
                #pragma unroll
                for (int q = 0; q < 4; q++) acc[mt][nt][q] = 0.f;

        #pragma unroll
        for (int ks = 0; ks < 8; ks++) {
            uint32_t kkb = (uint32_t)ks * 32u;
            uint32_t a[2][4], B[2][4];
            ldsm_x4(a[0], aBuf + aOff[0] + kkb);
            ldsm_x4(a[1], aBuf + aOff[1] + kkb);
            ldsm_x4(B[0], bAddr[0] + kkb);
            ldsm_x4(B[1], bAddr[1] + kkb);
            #pragma unroll
            for (int nt = 0; nt < 4; nt++) {
                uint32_t b0 = B[nt >> 1][(nt & 1) * 2];
                uint32_t b1 = B[nt >> 1][(nt & 1) * 2 + 1];
                mma_fp16(acc[0][nt], a[0], b0, b1);
                mma_fp16(acc[1][nt], a[1], b0, b1);
            }
        }
        __syncthreads();
        if (t + 2 < n)
            prefetchA(bid + (t + 2) * GRID_GEMM, smemBase + (uint32_t)(t & 1) * ATILE, tid);

        // register epilogue (tanh.approx): z = 0.5+0.5*ta, (1-z)*th = 0.5*(1-ta)*th
        int rA = lane >> 2;
        int cA = (lane & 3) * 2;
        float s0[2], s1[2];
        #pragma unroll
        for (int mt = 0; mt < 2; mt++) { s0[mt] = 0.f; s1[mt] = 0.f; }
        #pragma unroll
        for (int mt = 0; mt < 2; mt++) {
            #pragma unroll
            for (int ntc = 0; ntc < 2; ntc++) {
                const float* aZ = acc[mt][ntc];
                const float* aH = acc[mt][ntc + 2];
                int cbase = wn * 16 + ntc * 8 + cA;
                #pragma unroll
                for (int u = 0; u < 2; u++) {
                    int c = cbase + u;
                    float bz = sBZ[c], bh = sBH[c], w = sWl[c];
                    {
                        float ta = tanh_fast((aZ[u] + bz) * 0.5f);
                        float th = tanh_fast(aH[u] + bh);
                        float h  = fmaxf(0.5f * (1.f - ta) * th, 0.f);
                        s0[mt] = fmaf(h, w, s0[mt]);
                    }
                    {
                        float ta = tanh_fast((aZ[2 + u] + bz) * 0.5f);
                        float th = tanh_fast(aH[2 + u] + bh);
                        float h  = fmaxf(0.5f * (1.f - ta) * th, 0.f);
                        s1[mt] = fmaf(h, w, s1[mt]);
                    }
                }
            }
        }
        #pragma unroll
        for (int mt = 0; mt < 2; mt++) {
            s0[mt] += __shfl_xor_sync(0xffffffffu, s0[mt], 1);
            s0[mt] += __shfl_xor_sync(0xffffffffu, s0[mt], 2);
            s1[mt] += __shfl_xor_sync(0xffffffffu, s1[mt], 1);
            s1[mt] += __shfl_xor_sync(0xffffffffu, s1[mt], 2);
        }
        if ((lane & 3) == 0) {
            #pragma unroll
            for (int mt = 0; mt < 2; mt++) {
                int r = wm * 32 + mt * 16 + rA;
                sRed[r][wn]     = s0[mt];
                sRed[r + 8][wn] = s1[mt];
            }
        }
        __syncthreads();
        if (tid < TILE_ROWS) {
            float v = sRed[tid][0] + sRed[tid][1] + sRed[tid][2] + sRed[tid][3];
            int rg   = (bid + t * GRID_GEMM) * TILE_ROWS + tid;   // row' = node*8 + tt
            int node = rg >> 3;
            int tt   = rg & 7;
            out[tt * N_NODES + node] = v + blin0;
        }
    }
}

// ---------------- launch ----------------
extern "C" void kernel_launch(void* const* d_in, const int* in_sizes, int n_in,
                              void* d_out, int out_size)
{
    const float* x    = (const float*)d_in[0];
    const int*   ei   = (const int*)  d_in[1];
    const float* ew   = (const float*)d_in[2];
    const float* Wxz0 = (const float*)d_in[3];
    const float* Wxz1 = (const float*)d_in[4];
    const float* bxz  = (const float*)d_in[5];
    const float* bhz  = (const float*)d_in[8];
    const float* Wxh0 = (const float*)d_in[15];
    const float* Wxh1 = (const float*)d_in[16];
    const float* bxh  = (const float*)d_in[17];
    const float* bhh  = (const float*)d_in[20];
    const float* Wlin = (const float*)d_in[21];
    const float* blin = (const float*)d_in[22];
    float* out = (float*)d_out;

    cudaFuncSetAttribute(k_gemm, cudaFuncAttributeMaxDynamicSharedMemorySize, DSMEM_BYTES);

    const int NB_C = (XCHUNKS + 255) / 256;    // 12500 blocks

    k_prep0  <<<NB_C, 256>>>((const float4*)x, ei, ew);  // 1: transpose + deg + fill
    k_gather <<<(N_NODES * 32 + 255) / 256, 256>>>();    // 2: 1 warp/node, nw on the fly
    k_gemm   <<<GRID_GEMM, GTHREADS, DSMEM_BYTES>>>(Wxz0, Wxz1, Wxh0, Wxh1,
                                                    bxz, bhz, bxh, bhh, Wlin, blin, out);
}

// round 16
// speedup vs baseline: 1.3218x; 1.0002x over previous
#include <cuda_runtime.h>
#include <cuda_fp16.h>
#include <cstdint>
#include <cstddef>

#define T_DIM   8
#define N_NODES 50000
#define E_EDGES 800000
#define C_DIM   64
#define M_ROWS  (T_DIM * N_NODES)   // 400000 rows of [x | tx1]
#define BCAP    64                   // bucket capacity per node (P(deg>64) ~ 0)

// ---------------- scratch (static device globals; no allocation) ----------------
// g_deg / g_cnt are zeroed by k_gemm at the END of each invocation (and are
// zero at module load), so the prep path needs no separate zeroing kernel.
__device__ float   g_deg[N_NODES];
__device__ int     g_cnt[N_NODES];
__device__ uint2   g_cv[(size_t)N_NODES * BCAP];        // packed (src, raw ew) buckets
// node-major fp16: [node][t][32 half2] — 1KB per node
__device__ __half2 g_xh  [(size_t)M_ROWS * (C_DIM/2)];  // 51.2 MB
__device__ __half2 g_tx1h[(size_t)M_ROWS * (C_DIM/2)];  // 51.2 MB

// ---------------- prep0: DISJOINT thread ranges —
//   j <  XCHUNKS           : pure streaming x->fp16 node-major transpose
//   j >= XCHUNKS (e = j-X) : pure edge work (deg atomic + bucket fill, raw ew)
// ----------------------------------------------------------------------------
#define XCHUNKS (M_ROWS * 8)   // 3.2M 16-byte output chunks

__global__ void k_prep0(const float4* __restrict__ x4,
                        const int* __restrict__ ei, const float* __restrict__ ew) {
    int j = blockIdx.x * blockDim.x + threadIdx.x;
    if (j < XCHUNKS) {
        int c4 = j & 7;          // which 16B chunk within the 128B t-row
        int r  = j >> 3;         // node-major row = n*8 + t
        int n  = r >> 3;
        int t  = r & 7;
        size_t s = ((size_t)t * N_NODES + n) * 16 + (size_t)c4 * 2;
        float4 v0 = __ldg(&x4[s]);
        float4 v1 = __ldg(&x4[s + 1]);
        uint4 o;
        __half2 h;
        h = __floats2half2_rn(v0.x, v0.y); o.x = *(uint32_t*)&h;
        h = __floats2half2_rn(v0.z, v0.w); o.y = *(uint32_t*)&h;
        h = __floats2half2_rn(v1.x, v1.y); o.z = *(uint32_t*)&h;
        h = __floats2half2_rn(v1.z, v1.w); o.w = *(uint32_t*)&h;
        ((uint4*)g_xh)[j] = o;
    } else {
        int e = j - XCHUNKS;
        if (e < E_EDGES) {
            int s = ei[e];
            int d = ei[E_EDGES + e];
            float w = ew[e];
            atomicAdd(&g_deg[s], w);            // g_deg pre-zeroed by prior k_gemm
            int p = atomicAdd(&g_cnt[d], 1);    // g_cnt pre-zeroed by prior k_gemm
            if (p < BCAP) {
                uint2 cv;
                cv.x = (uint32_t)s;
                cv.y = __float_as_uint(w);      // raw weight; normalized in gather
                g_cv[((size_t)d << 6) + p] = cv;
            }
        }
    }
}

// ---------------- gather: one warp per dst node, lane owns 32B slice;
//                  nw computed on the fly (dinv hidden under L2 latency) ----------------
__device__ __forceinline__ float dinv_of(float dg) {
    return (dg > 0.f) ? rsqrtf(fmaxf(dg, 1e-12f)) : 0.f;
}

__global__ void k_gather() {
    int warp = (blockIdx.x * blockDim.x + threadIdx.x) >> 5;
    int lane = threadIdx.x & 31;
    if (warp >= N_NODES) return;
    int cnt = 0;
    float dinvD = 0.f;
    if (lane == 0) {
        cnt = g_cnt[warp];
        dinvD = dinv_of(g_deg[warp]);
    }
    cnt   = __shfl_sync(0xffffffffu, cnt, 0);
    dinvD = __shfl_sync(0xffffffffu, dinvD, 0);
    if (cnt > BCAP) cnt = BCAP;
    const uint2* __restrict__ bucket = g_cv + ((size_t)warp << 6);

    float2 acc[8];
    #pragma unroll
    for (int q = 0; q < 8; q++) acc[q] = make_float2(0.f, 0.f);

    const char* xbase = (const char*)g_xh + (size_t)lane * 32;

    int e = 0;
    for (; e + 1 < cnt; e += 2) {
        uint2 cv0 = __ldg(&bucket[e]);
        uint2 cv1 = __ldg(&bucket[e + 1]);
        float v0 = -__uint_as_float(cv0.y) * dinv_of(__ldg(&g_deg[cv0.x])) * dinvD;
        float v1 = -__uint_as_float(cv1.y) * dinv_of(__ldg(&g_deg[cv1.x])) * dinvD;
        const uint4* p0 = (const uint4*)(xbase + (size_t)cv0.x * 1024);
        const uint4* p1 = (const uint4*)(xbase + (size_t)cv1.x * 1024);
        uint4 a0 = __ldg(p0), b0 = __ldg(p0 + 1);
        uint4 a1 = __ldg(p1), b1 = __ldg(p1 + 1);
        const uint32_t* w0 = (const uint32_t*)&a0;
        const uint32_t* u0 = (const uint32_t*)&b0;
        const uint32_t* w1 = (const uint32_t*)&a1;
        const uint32_t* u1 = (const uint32_t*)&b1;
        #pragma unroll
        for (int q = 0; q < 4; q++) {
            float2 f;
            f = __half22float2(*(const __half2*)&w0[q]);
            acc[q].x = fmaf(v0, f.x, acc[q].x); acc[q].y = fmaf(v0, f.y, acc[q].y);
            f = __half22float2(*(const __half2*)&u0[q]);
            acc[4+q].x = fmaf(v0, f.x, acc[4+q].x); acc[4+q].y = fmaf(v0, f.y, acc[4+q].y);
            f = __half22float2(*(const __half2*)&w1[q]);
            acc[q].x = fmaf(v1, f.x, acc[q].x); acc[q].y = fmaf(v1, f.y, acc[q].y);
            f = __half22float2(*(const __half2*)&u1[q]);
            acc[4+q].x = fmaf(v1, f.x, acc[4+q].x); acc[4+q].y = fmaf(v1, f.y, acc[4+q].y);
        }
    }
    if (e < cnt) {
        uint2 cv0 = __ldg(&bucket[e]);
        float v0 = -__uint_as_float(cv0.y) * dinv_of(__ldg(&g_deg[cv0.x])) * dinvD;
        const uint4* p0 = (const uint4*)(xbase + (size_t)cv0.x * 1024);
        uint4 a0 = __ldg(p0), b0 = __ldg(p0 + 1);
        const uint32_t* w0 = (const uint32_t*)&a0;
        const uint32_t* u0 = (const uint32_t*)&b0;
        #pragma unroll
        for (int q = 0; q < 4; q++) {
            float2 f;
            f = __half22float2(*(const __half2*)&w0[q]);
            acc[q].x = fmaf(v0, f.x, acc[q].x); acc[q].y = fmaf(v0, f.y, acc[q].y);
            f = __half22float2(*(const __half2*)&u0[q]);
            acc[4+q].x = fmaf(v0, f.x, acc[4+q].x); acc[4+q].y = fmaf(v0, f.y, acc[4+q].y);
        }
    }

    uint4 o0, o1;
    uint32_t* w = (uint32_t*)&o0;
    uint32_t* u = (uint32_t*)&o1;
    #pragma unroll
    for (int q = 0; q < 4; q++) {
        __half2 h0 = __floats2half2_rn(acc[q].x, acc[q].y);
        __half2 h1 = __floats2half2_rn(acc[4+q].x, acc[4+q].y);
        w[q] = *(uint32_t*)&h0;
        u[q] = *(uint32_t*)&h1;
    }
    uint4* op = (uint4*)((char*)g_tx1h + (size_t)warp * 1024 + (size_t)lane * 32);
    op[0] = o0;
    op[1] = o1;
}

// ============================================================================
// HMMA fp16 GEMM — 2 CTAs/SM: grid 296, 256 threads, 64x128 tile, warp = 32x32,
// ldmatrix frags, 2-stage cp.async, tanh.approx epilogue.
// Zeroes g_cnt/g_deg for next invocation.
// ============================================================================

#define TILE_ROWS 64
#define TILES     (M_ROWS / TILE_ROWS)   // 6250
#define GRID_GEMM 296
#define GTHREADS  256

#define ASTRIDE 272u
#define ATILE   ((uint32_t)TILE_ROWS * ASTRIDE)   // 17408
#define NBUF    2
#define OFF_W   (NBUF * ATILE)
#define WTILE   (128u * ASTRIDE)                  // 34816 (W is 128x128)
#define DSMEM_BYTES (NBUF * ATILE + WTILE)        // 69632

#define CP_ASYNC16(dst, src) \
    asm volatile("cp.async.cg.shared.global [%0], [%1], 16;" :: "r"(dst), "l"(src))
#define CP_COMMIT() asm volatile("cp.async.commit_group;" ::: "memory")
#define CP_WAIT(n)  asm volatile("cp.async.wait_group %0;" :: "n"(n) : "memory")

__device__ __forceinline__ void mma_fp16(float* c, const uint32_t* a,
                                         uint32_t b0, uint32_t b1) {
    asm volatile(
        "mma.sync.aligned.m16n8k16.row.col.f32.f16.f16.f32 "
        "{%0,%1,%2,%3}, {%4,%5,%6,%7}, {%8,%9}, {%0,%1,%2,%3};"
        : "+f"(c[0]), "+f"(c[1]), "+f"(c[2]), "+f"(c[3])
        : "r"(a[0]), "r"(a[1]), "r"(a[2]), "r"(a[3]), "r"(b0), "r"(b1));
}

__device__ __forceinline__ void ldsm_x4(uint32_t* d, uint32_t addr) {
    asm volatile("ldmatrix.sync.aligned.m8n8.x4.shared.b16 {%0,%1,%2,%3}, [%4];"
                 : "=r"(d[0]), "=r"(d[1]), "=r"(d[2]), "=r"(d[3]) : "r"(addr));
}

__device__ __forceinline__ float tanh_fast(float x) {
    float r;
    asm("tanh.approx.f32 %0, %1;" : "=f"(r) : "f"(x));
    return r;
}

__device__ __forceinline__ void prefetchA(int tile, uint32_t dstBase, int tid) {
    int rowBase = tile * TILE_ROWS;
    #pragma unroll
    for (int it = 0; it < 4; it++) {
        int chunk = tid + it * GTHREADS;   // 0..1023 chunks of 16B (64 rows x 16)
        int r   = chunk >> 4;
        int c16 = chunk & 15;
        size_t row = (size_t)(rowBase + r);
        const void* src = (c16 < 8)
            ? (const void*)(g_xh   + row * 32 + c16 * 4)
            : (const void*)(g_tx1h + row * 32 + (c16 - 8) * 4);
        uint32_t dst = dstBase + (uint32_t)r * ASTRIDE + (uint32_t)c16 * 16u;
        CP_ASYNC16(dst, src);
    }
    CP_COMMIT();
}

__global__ void __launch_bounds__(GTHREADS, 2) k_gemm(
    const float* __restrict__ Wxz0, const float* __restrict__ Wxz1,
    const float* __restrict__ Wxh0, const float* __restrict__ Wxh1,
    const float* __restrict__ bxz,  const float* __restrict__ bhz,
    const float* __restrict__ bxh,  const float* __restrict__ bhh,
    const float* __restrict__ wlin, const float* __restrict__ blin,
    float* __restrict__ out)
{
    extern __shared__ char dsm[];
    __shared__ float sBZ[64], sBH[64], sWl[64];
    __shared__ float sRed[TILE_ROWS][4];

    char* WTh = dsm + OFF_W;
    uint32_t smemBase = (uint32_t)__cvta_generic_to_shared(dsm);
    uint32_t smemW32  = smemBase + OFF_W;

    int tid  = threadIdx.x;
    int wid  = tid >> 5;
    int lane = tid & 31;
    int bid  = blockIdx.x;
    int n = (TILES - bid + GRID_GEMM - 1) / GRID_GEMM;

    // zero cnt/deg for the NEXT kernel_launch invocation
    for (int i = bid * GTHREADS + tid; i < N_NODES; i += GRID_GEMM * GTHREADS) {
        g_cnt[i] = 0;
        g_deg[i] = 0.f;
    }

    int wm = wid >> 2;           // 0..1 : rows wm*32 ..
    int wn = wid & 3;            // 0..3 : Z cols wn*16.., H cols 64+wn*16..

    for (int idx = tid; idx < 16384; idx += GTHREADS) {
        int nn = idx >> 7;
        int k  = idx & 127;
        float v;
        if (k < 64) v = (nn < 64) ? Wxz0[k * 64 + nn]        : Wxh0[k * 64 + (nn - 64)];
        else        v = (nn < 64) ? Wxz1[(k - 64) * 64 + nn] : Wxh1[(k - 64) * 64 + (nn - 64)];
        *(__half*)(WTh + (uint32_t)nn * ASTRIDE + (uint32_t)k * 2u) = __float2half_rn(v);
    }
    if (tid < 64) {
        sBZ[tid] = bxz[tid] + bhz[tid];
        sBH[tid] = bxh[tid] + bhh[tid];
        sWl[tid] = wlin[tid];
    }
    float blin0 = blin[0];

    // ldmatrix per-lane addresses
    uint32_t aOff[2];   // relative to A-buffer base
    uint32_t bAddr[2];  // absolute (W tile fixed)
    {
        int m = lane >> 3, r = lane & 7;
        #pragma unroll
        for (int mt = 0; mt < 2; mt++) {
            int rowA = wm * 32 + mt * 16 + ((m & 1) << 3) + r;
            aOff[mt] = (uint32_t)rowA * ASTRIDE + (uint32_t)((m >> 1) << 4);
        }
        int q = lane >> 3;
        #pragma unroll
        for (int g = 0; g < 2; g++) {
            int nt  = g * 2 + (q >> 1);
            int col = wn * 16 + ((nt & 1) << 3) + ((nt >> 1) << 6);
            bAddr[g] = smemW32 + (uint32_t)(col + r) * ASTRIDE + (uint32_t)((q & 1) << 4);
        }
    }

    prefetchA(bid, smemBase, tid);
    if (n > 1) prefetchA(bid + GRID_GEMM, smemBase + ATILE, tid);

    for (int t = 0; t < n; t++) {
        if (t + 1 < n) { CP_WAIT(1); }
        else           { CP_WAIT(0); }
        __syncthreads();

        uint32_t aBuf = smemBase + (uint32_t)(t & 1) * ATILE;

        float acc[2][4][4];
        #pragma unroll
        for (int mt = 0; mt < 2; mt++)
            #pragma unroll
            for (int nt = 0; nt < 4; nt++)
                #pragma unroll
                for (int q = 0; q < 4; q++) acc[mt][nt][q] = 0.f;

        #pragma unroll
        for (int ks = 0; ks < 8; ks++) {
            uint32_t kkb = (uint32_t)ks * 32u;
            uint32_t a[2][4], B[2][4];
            ldsm_x4(a[0], aBuf + aOff[0] + kkb);
            ldsm_x4(a[1], aBuf + aOff[1] + kkb);
            ldsm_x4(B[0], bAddr[0] + kkb);
            ldsm_x4(B[1], bAddr[1] + kkb);
            #pragma unroll
            for (int nt = 0; nt < 4; nt++) {
                uint32_t b0 = B[nt >> 1][(nt & 1) * 2];
                uint32_t b1 = B[nt >> 1][(nt & 1) * 2 + 1];
                mma_fp16(acc[0][nt], a[0], b0, b1);
                mma_fp16(acc[1][nt], a[1], b0, b1);
            }
        }
        __syncthreads();
        if (t + 2 < n)
            prefetchA(bid + (t + 2) * GRID_GEMM, smemBase + (uint32_t)(t & 1) * ATILE, tid);

        // register epilogue (tanh.approx): z = 0.5+0.5*ta, (1-z)*th = 0.5*(1-ta)*th
        int rA = lane >> 2;
        int cA = (lane & 3) * 2;
        float s0[2], s1[2];
        #pragma unroll
        for (int mt = 0; mt < 2; mt++) { s0[mt] = 0.f; s1[mt] = 0.f; }
        #pragma unroll
        for (int mt = 0; mt < 2; mt++) {
            #pragma unroll
            for (int ntc = 0; ntc < 2; ntc++) {
                const float* aZ = acc[mt][ntc];
                const float* aH = acc[mt][ntc + 2];
                int cbase = wn * 16 + ntc * 8 + cA;
                #pragma unroll
                for (int u = 0; u < 2; u++) {
                    int c = cbase + u;
                    float bz = sBZ[c], bh = sBH[c], w = sWl[c];
                    {
                        float ta = tanh_fast((aZ[u] + bz) * 0.5f);
                        float th = tanh_fast(aH[u] + bh);
                        float h  = fmaxf(0.5f * (1.f - ta) * th, 0.f);
                        s0[mt] = fmaf(h, w, s0[mt]);
                    }
                    {
                        float ta = tanh_fast((aZ[2 + u] + bz) * 0.5f);
                        float th = tanh_fast(aH[2 + u] + bh);
                        float h  = fmaxf(0.5f * (1.f - ta) * th, 0.f);
                        s1[mt] = fmaf(h, w, s1[mt]);
                    }
                }
            }
        }
        #pragma unroll
        for (int mt = 0; mt < 2; mt++) {
            s0[mt] += __shfl_xor_sync(0xffffffffu, s0[mt], 1);
            s0[mt] += __shfl_xor_sync(0xffffffffu, s0[mt], 2);
            s1[mt] += __shfl_xor_sync(0xffffffffu, s1[mt], 1);
            s1[mt] += __shfl_xor_sync(0xffffffffu, s1[mt], 2);
        }
        if ((lane & 3) == 0) {
            #pragma unroll
            for (int mt = 0; mt < 2; mt++) {
                int r = wm * 32 + mt * 16 + rA;
                sRed[r][wn]     = s0[mt];
                sRed[r + 8][wn] = s1[mt];
            }
        }
        __syncthreads();
        if (tid < TILE_ROWS) {
            float v = sRed[tid][0] + sRed[tid][1] + sRed[tid][2] + sRed[tid][3];
            int rg   = (bid + t * GRID_GEMM) * TILE_ROWS + tid;   // row' = node*8 + tt
            int node = rg >> 3;
            int tt   = rg & 7;
            out[tt * N_NODES + node] = v + blin0;
        }
    }
}

// ---------------- launch ----------------
extern "C" void kernel_launch(void* const* d_in, const int* in_sizes, int n_in,
                              void* d_out, int out_size)
{
    const float* x    = (const float*)d_in[0];
    const int*   ei   = (const int*)  d_in[1];
    const float* ew   = (const float*)d_in[2];
    const float* Wxz0 = (const float*)d_in[3];
    const float* Wxz1 = (const float*)d_in[4];
    const float* bxz  = (const float*)d_in[5];
    const float* bhz  = (const float*)d_in[8];
    const float* Wxh0 = (const float*)d_in[15];
    const float* Wxh1 = (const float*)d_in[16];
    const float* bxh  = (const float*)d_in[17];
    const float* bhh  = (const float*)d_in[20];
    const float* Wlin = (const float*)d_in[21];
    const float* blin = (const float*)d_in[22];
    float* out = (float*)d_out;

    cudaFuncSetAttribute(k_gemm, cudaFuncAttributeMaxDynamicSharedMemorySize, DSMEM_BYTES);

    const int NB_P = (XCHUNKS + E_EDGES + 255) / 256;   // 15625 blocks, disjoint jobs

    k_prep0  <<<NB_P, 256>>>((const float4*)x, ei, ew);  // 1: transpose ∥ deg+fill
    k_gather <<<(N_NODES * 32 + 255) / 256, 256>>>();    // 2: 1 warp/node, nw on the fly
    k_gemm   <<<GRID_GEMM, GTHREADS, DSMEM_BYTES>>>(Wxz0, Wxz1, Wxh0, Wxh1,
                                                    bxz, bhz, bxh, bhh, Wlin, blin, out);
}